// round 2
// baseline (speedup 1.0000x reference)
#include <cuda_runtime.h>
#include <math.h>

#define Bb   4
#define Tdim 2048
#define Cdim 2048
#define BT   8192        // Bb*Tdim
#define H    16
#define HD   128
#define Rr   128
#define NB   16
#define BS   128
#define NBH  64          // Bb*H

static const float SCALE_ATT = 0.08838834764831845f; // 1/sqrt(128)

// scratch (device globals: no allocation allowed)
__device__ float g_t[(size_t)BT * Rr];
__device__ float g_q[(size_t)Bb * Tdim * Cdim];
__device__ float g_k[(size_t)Bb * Tdim * Cdim];
__device__ float g_v[(size_t)Bb * Tdim * Cdim];
__device__ float g_y[(size_t)Bb * Tdim * Cdim];
__device__ float g_S[(size_t)NBH * Tdim * Tdim]; // ~1.07 GB attention scores

// ---------------------------------------------------------------------------
// K1: t[M][128] = X[M][2048] @ L[128][2048]^T   (64x64 tile, 4x4 per thread)
// ---------------------------------------------------------------------------
__global__ void left_proj_kernel(const float* __restrict__ X,
                                 const float* __restrict__ L,
                                 float* __restrict__ Tout) {
    const int BK = 16;
    __shared__ __align__(16) float As[BK][64];
    __shared__ __align__(16) float Bs[BK][64];
    int tid = threadIdx.x;
    int tx = tid & 15, ty = tid >> 4;
    int m0 = blockIdx.x * 64, n0 = blockIdx.y * 64;
    float acc[4][4] = {};
    for (int k0 = 0; k0 < Cdim; k0 += BK) {
        int r = tid >> 2, kq = (tid & 3) << 2;
        float4 v = *(const float4*)(X + (size_t)(m0 + r) * Cdim + k0 + kq);
        As[kq + 0][r] = v.x; As[kq + 1][r] = v.y; As[kq + 2][r] = v.z; As[kq + 3][r] = v.w;
        float4 w = *(const float4*)(L + (size_t)(n0 + r) * Cdim + k0 + kq);
        Bs[kq + 0][r] = w.x; Bs[kq + 1][r] = w.y; Bs[kq + 2][r] = w.z; Bs[kq + 3][r] = w.w;
        __syncthreads();
#pragma unroll
        for (int k = 0; k < BK; k++) {
            float4 a = *(const float4*)&As[k][ty * 4];
            float4 b = *(const float4*)&Bs[k][tx * 4];
            float ar[4] = {a.x, a.y, a.z, a.w};
            float br[4] = {b.x, b.y, b.z, b.w};
#pragma unroll
            for (int i = 0; i < 4; i++)
#pragma unroll
                for (int j = 0; j < 4; j++) acc[i][j] += ar[i] * br[j];
        }
        __syncthreads();
    }
    for (int i = 0; i < 4; i++)
        for (int j = 0; j < 4; j++)
            Tout[(size_t)(m0 + ty * 4 + i) * Rr + n0 + tx * 4 + j] = acc[i][j];
}

// ---------------------------------------------------------------------------
// K2: fused LORI output:
//   Y[m][c0+e] = sum_d X[m][c0+d]*D[d][e] + sum_r Tl[m][r]*RW[c0+e][r]
//               + rb[c0+e] + bp[c0+e]
// 64(bt) x 128(e) tile per block; grid = (BT/64, NB)
// ---------------------------------------------------------------------------
__global__ void fused_out_kernel(const float* __restrict__ X,
                                 const float* __restrict__ Tl,
                                 const float* __restrict__ Dg,
                                 const float* __restrict__ RW,
                                 const float* __restrict__ rb,
                                 const float* __restrict__ bp,
                                 float* __restrict__ Y) {
    const int BK = 16;
    __shared__ __align__(16) float As[BK][64];
    __shared__ __align__(16) float Ws[BK][128];
    int tid = threadIdx.x;
    int tx = tid & 15, ty = tid >> 4;
    int m0 = blockIdx.x * 64;
    int nb = blockIdx.y;
    int c0 = nb * BS;
    const float* D = Dg + (size_t)nb * BS * BS;
    float acc[4][8] = {};

    // phase 1: block-diagonal (K = 128 over d)
    for (int k0 = 0; k0 < BS; k0 += BK) {
        {   // As[k][m] = X[m0+m][c0+k0+k]  (transpose-load)
            int r = tid >> 2, kq = (tid & 3) << 2;
            float4 v = *(const float4*)(X + (size_t)(m0 + r) * Cdim + c0 + k0 + kq);
            As[kq + 0][r] = v.x; As[kq + 1][r] = v.y; As[kq + 2][r] = v.z; As[kq + 3][r] = v.w;
        }
        // Ws[k][e] = D[(k0+k)*128 + e]   (direct, 2 float4/thread)
        for (int p = 0; p < 2; p++) {
            int idx = tid + p * 256;
            int k = idx >> 5, e4 = (idx & 31) << 2;
            *(float4*)&Ws[k][e4] = *(const float4*)(D + (size_t)(k0 + k) * BS + e4);
        }
        __syncthreads();
#pragma unroll
        for (int k = 0; k < BK; k++) {
            float4 a  = *(const float4*)&As[k][ty * 4];
            float4 b0 = *(const float4*)&Ws[k][tx * 8];
            float4 b1 = *(const float4*)&Ws[k][tx * 8 + 4];
            float ar[4] = {a.x, a.y, a.z, a.w};
            float br[8] = {b0.x, b0.y, b0.z, b0.w, b1.x, b1.y, b1.z, b1.w};
#pragma unroll
            for (int i = 0; i < 4; i++)
#pragma unroll
                for (int j = 0; j < 8; j++) acc[i][j] += ar[i] * br[j];
        }
        __syncthreads();
    }

    // phase 2: low-rank (K = 128 over r)
    for (int k0 = 0; k0 < Rr; k0 += BK) {
        {   // As[k][m] = Tl[m0+m][k0+k]
            int r = tid >> 2, kq = (tid & 3) << 2;
            float4 v = *(const float4*)(Tl + (size_t)(m0 + r) * Rr + k0 + kq);
            As[kq + 0][r] = v.x; As[kq + 1][r] = v.y; As[kq + 2][r] = v.z; As[kq + 3][r] = v.w;
        }
        // Ws[k][e] = RW[(c0+e)*128 + k0+k]  (transpose-load, 2 float4/thread)
        for (int p = 0; p < 2; p++) {
            int idx = tid + p * 256;
            int e = idx >> 2, kq = (idx & 3) << 2;
            float4 v = *(const float4*)(RW + (size_t)(c0 + e) * Rr + k0 + kq);
            Ws[kq + 0][e] = v.x; Ws[kq + 1][e] = v.y; Ws[kq + 2][e] = v.z; Ws[kq + 3][e] = v.w;
        }
        __syncthreads();
#pragma unroll
        for (int k = 0; k < BK; k++) {
            float4 a  = *(const float4*)&As[k][ty * 4];
            float4 b0 = *(const float4*)&Ws[k][tx * 8];
            float4 b1 = *(const float4*)&Ws[k][tx * 8 + 4];
            float ar[4] = {a.x, a.y, a.z, a.w};
            float br[8] = {b0.x, b0.y, b0.z, b0.w, b1.x, b1.y, b1.z, b1.w};
#pragma unroll
            for (int i = 0; i < 4; i++)
#pragma unroll
                for (int j = 0; j < 8; j++) acc[i][j] += ar[i] * br[j];
        }
        __syncthreads();
    }

    for (int i = 0; i < 4; i++)
        for (int j = 0; j < 8; j++) {
            int c = c0 + tx * 8 + j;
            Y[(size_t)(m0 + ty * 4 + i) * Cdim + c] = acc[i][j] + rb[c] + bp[c];
        }
}

// ---------------------------------------------------------------------------
// K3: S tile = scale * Q_tile @ K_tile^T  (only causal tiles kt <= qt)
// grid = (kt=32, qt=32, bh=64)
// ---------------------------------------------------------------------------
__global__ void scores_kernel(const float* __restrict__ Q, const float* __restrict__ Kb) {
    int kt = blockIdx.x, qt = blockIdx.y, bh = blockIdx.z;
    if (kt > qt) return;
    int b = bh / H, h = bh % H;
    const float* Qp = Q + (size_t)b * Tdim * Cdim + (size_t)h * HD;
    const float* Kp = Kb + (size_t)b * Tdim * Cdim + (size_t)h * HD;
    const int BK = 16;
    __shared__ __align__(16) float As[BK][64];
    __shared__ __align__(16) float Bs[BK][64];
    int tid = threadIdx.x;
    int tx = tid & 15, ty = tid >> 4;
    int m0 = qt * 64, n0 = kt * 64;
    float acc[4][4] = {};
    for (int k0 = 0; k0 < HD; k0 += BK) {
        int r = tid >> 2, kq = (tid & 3) << 2;
        float4 v = *(const float4*)(Qp + (size_t)(m0 + r) * Cdim + k0 + kq);
        As[kq + 0][r] = v.x; As[kq + 1][r] = v.y; As[kq + 2][r] = v.z; As[kq + 3][r] = v.w;
        float4 w = *(const float4*)(Kp + (size_t)(n0 + r) * Cdim + k0 + kq);
        Bs[kq + 0][r] = w.x; Bs[kq + 1][r] = w.y; Bs[kq + 2][r] = w.z; Bs[kq + 3][r] = w.w;
        __syncthreads();
#pragma unroll
        for (int k = 0; k < BK; k++) {
            float4 a = *(const float4*)&As[k][ty * 4];
            float4 b2 = *(const float4*)&Bs[k][tx * 4];
            float ar[4] = {a.x, a.y, a.z, a.w};
            float br[4] = {b2.x, b2.y, b2.z, b2.w};
#pragma unroll
            for (int i = 0; i < 4; i++)
#pragma unroll
                for (int j = 0; j < 4; j++) acc[i][j] += ar[i] * br[j];
        }
        __syncthreads();
    }
    float* Sp = g_S + (size_t)bh * Tdim * Tdim;
    for (int i = 0; i < 4; i++)
        for (int j = 0; j < 4; j++)
            Sp[(size_t)(m0 + ty * 4 + i) * Tdim + n0 + tx * 4 + j] = acc[i][j] * SCALE_ATT;
}

// ---------------------------------------------------------------------------
// K4: causal softmax, one warp per row; zero-fills diag-tile remainder.
// ---------------------------------------------------------------------------
__global__ void softmax_kernel() {
    int gw = (blockIdx.x * blockDim.x + threadIdx.x) >> 5;
    int lane = threadIdx.x & 31;
    int bh = gw / Tdim;
    int q = gw % Tdim;
    float* p = g_S + (size_t)bh * Tdim * Tdim + (size_t)q * Tdim;
    int len = q + 1;
    float m = -1e30f;
    for (int j = lane; j < len; j += 32) m = fmaxf(m, p[j]);
#pragma unroll
    for (int o = 16; o; o >>= 1) m = fmaxf(m, __shfl_xor_sync(0xffffffffu, m, o));
    float s = 0.f;
    for (int j = lane; j < len; j += 32) {
        float e = __expf(p[j] - m);
        p[j] = e;
        s += e;
    }
#pragma unroll
    for (int o = 16; o; o >>= 1) s += __shfl_xor_sync(0xffffffffu, s, o);
    float inv = 1.0f / s;
    for (int j = lane; j < len; j += 32) p[j] *= inv;
    int jend = ((q >> 6) + 1) << 6; // end of diagonal 64-tile
    for (int j = len + lane; j < jend; j += 32) p[j] = 0.f;
}

// ---------------------------------------------------------------------------
// K5: Y[q][d] = sum_{j<=causal} P[q][j] * V[j][d]   (64 x 128 tile)
// grid = (qt=32, bh=64)
// ---------------------------------------------------------------------------
__global__ void pv_kernel(const float* __restrict__ V, float* __restrict__ Y) {
    int qt = blockIdx.x, bh = blockIdx.y;
    int b = bh / H, h = bh % H;
    const float* Sp = g_S + (size_t)bh * Tdim * Tdim;
    const float* Vp = V + (size_t)b * Tdim * Cdim + (size_t)h * HD;
    float* Yp = Y + (size_t)b * Tdim * Cdim + (size_t)h * HD;
    const int BK = 16;
    __shared__ __align__(16) float As[BK][64];
    __shared__ __align__(16) float Ws[BK][128];
    int tid = threadIdx.x;
    int tx = tid & 15, ty = tid >> 4;
    int m0 = qt * 64;
    float acc[4][8] = {};
    int klen = (qt + 1) * 64;
    for (int k0 = 0; k0 < klen; k0 += BK) {
        {   // As[k][q] = P[m0+q][k0+k]
            int r = tid >> 2, kq = (tid & 3) << 2;
            float4 v = *(const float4*)(Sp + (size_t)(m0 + r) * Tdim + k0 + kq);
            As[kq + 0][r] = v.x; As[kq + 1][r] = v.y; As[kq + 2][r] = v.z; As[kq + 3][r] = v.w;
        }
        // Ws[k][d] = V[(k0+k)][d]
        for (int p = 0; p < 2; p++) {
            int idx = tid + p * 256;
            int k = idx >> 5, e4 = (idx & 31) << 2;
            *(float4*)&Ws[k][e4] = *(const float4*)(Vp + (size_t)(k0 + k) * Cdim + e4);
        }
        __syncthreads();
#pragma unroll
        for (int k = 0; k < BK; k++) {
            float4 a  = *(const float4*)&As[k][ty * 4];
            float4 b0 = *(const float4*)&Ws[k][tx * 8];
            float4 b1 = *(const float4*)&Ws[k][tx * 8 + 4];
            float ar[4] = {a.x, a.y, a.z, a.w};
            float br[8] = {b0.x, b0.y, b0.z, b0.w, b1.x, b1.y, b1.z, b1.w};
#pragma unroll
            for (int i = 0; i < 4; i++)
#pragma unroll
                for (int j = 0; j < 8; j++) acc[i][j] += ar[i] * br[j];
        }
        __syncthreads();
    }
    for (int i = 0; i < 4; i++)
        for (int j = 0; j < 8; j++)
            Yp[(size_t)(m0 + ty * 4 + i) * Cdim + tx * 8 + j] = acc[i][j];
}

// ---------------------------------------------------------------------------
extern "C" void kernel_launch(void* const* d_in, const int* in_sizes, int n_in,
                              void* d_out, int out_size) {
    const float* x    = (const float*)d_in[0];
    const float* diag = (const float*)d_in[1];
    const float* left = (const float*)d_in[2];
    const float* rw   = (const float*)d_in[3];
    const float* rb   = (const float*)d_in[4];
    const float* bp   = (const float*)d_in[5];
    float* out = (float*)d_out;

    float *pt, *pq, *pk, *pv, *py;
    cudaGetSymbolAddress((void**)&pt, g_t);
    cudaGetSymbolAddress((void**)&pq, g_q);
    cudaGetSymbolAddress((void**)&pk, g_k);
    cudaGetSymbolAddress((void**)&pv, g_v);
    cudaGetSymbolAddress((void**)&py, g_y);

    float* dst[3] = {pq, pk, pv};
    for (int i = 0; i < 3; i++) {
        left_proj_kernel<<<dim3(BT / 64, Rr / 64), 256>>>(
            x, left + (size_t)i * Rr * Cdim, pt);
        fused_out_kernel<<<dim3(BT / 64, NB), 256>>>(
            x, pt,
            diag + (size_t)i * NB * BS * BS,
            rw + (size_t)i * Cdim * Rr,
            rb + (size_t)i * Cdim,
            bp + (size_t)i * Cdim,
            dst[i]);
    }

    scores_kernel<<<dim3(32, 32, NBH), 256>>>(pq, pk);
    softmax_kernel<<<(NBH * Tdim) / 8, 256>>>();
    pv_kernel<<<dim3(32, NBH), 256>>>(pv, py);

    left_proj_kernel<<<dim3(BT / 64, Rr / 64), 256>>>(
        py, left + (size_t)3 * Rr * Cdim, pt);
    fused_out_kernel<<<dim3(BT / 64, NB), 256>>>(
        py, pt,
        diag + (size_t)3 * NB * BS * BS,
        rw + (size_t)3 * Cdim * Rr,
        rb + (size_t)3 * Cdim,
        bp + (size_t)3 * Cdim,
        out);
}

// round 3
// speedup vs baseline: 2.5366x; 2.5366x over previous
#include <cuda_runtime.h>
#include <math.h>

#define Bb   4
#define Tdim 2048
#define Cdim 2048
#define BT   8192        // Bb*Tdim
#define H    16
#define HD   128
#define Rr   128
#define NB   16
#define BS   128
#define NBH  64          // Bb*H

static const float SCALE_ATT = 0.08838834764831845f; // 1/sqrt(128)

// scratch (device globals: no allocation allowed)
__device__ float g_t[(size_t)BT * Rr];
__device__ float g_q[(size_t)Bb * Tdim * Cdim];
__device__ float g_k[(size_t)Bb * Tdim * Cdim];
__device__ float g_v[(size_t)Bb * Tdim * Cdim];
__device__ float g_y[(size_t)Bb * Tdim * Cdim];
__device__ float g_S[(size_t)NBH * Tdim * Tdim]; // ~1.07 GB attention scores

// ---------------------------------------------------------------------------
// tf32 mma helpers
// ---------------------------------------------------------------------------
__device__ __forceinline__ unsigned f2tf32(float f) {
    unsigned r;
    asm("cvt.rna.tf32.f32 %0, %1;" : "=r"(r) : "f"(f));
    return r;
}

__device__ __forceinline__ void mma_tf32(float* c, const unsigned* a, const unsigned* b) {
    asm volatile(
        "mma.sync.aligned.m16n8k8.row.col.f32.tf32.tf32.f32 "
        "{%0,%1,%2,%3}, {%4,%5,%6,%7}, {%8,%9}, {%0,%1,%2,%3};\n"
        : "+f"(c[0]), "+f"(c[1]), "+f"(c[2]), "+f"(c[3])
        : "r"(a[0]), "r"(a[1]), "r"(a[2]), "r"(a[3]), "r"(b[0]), "r"(b[1]));
}

// A tile: 128 rows x 32 k, row-major source with leading dim ld (pre-offset ptr)
__device__ __forceinline__ void load_A(const float* __restrict__ A, int ld, int tid,
                                       unsigned (*As)[36]) {
#pragma unroll
    for (int p = 0; p < 4; p++) {
        int idx = tid + p * 256;
        int row = idx >> 3, c4 = (idx & 7) << 2;
        float4 v = *(const float4*)(A + (size_t)row * ld + c4);
        As[row][c4 + 0] = f2tf32(v.x); As[row][c4 + 1] = f2tf32(v.y);
        As[row][c4 + 2] = f2tf32(v.z); As[row][c4 + 3] = f2tf32(v.w);
    }
}

// B tile from weight stored [k][n] (32 x 128), direct into k-major Bs[k][n]
__device__ __forceinline__ void load_B_kn(const float* __restrict__ B, int ld, int tid,
                                          unsigned (*Bs)[132]) {
#pragma unroll
    for (int p = 0; p < 4; p++) {
        int idx = tid + p * 256;
        int kr = idx >> 5, n4 = (idx & 31) << 2;
        float4 v = *(const float4*)(B + (size_t)kr * ld + n4);
        Bs[kr][n4 + 0] = f2tf32(v.x); Bs[kr][n4 + 1] = f2tf32(v.y);
        Bs[kr][n4 + 2] = f2tf32(v.z); Bs[kr][n4 + 3] = f2tf32(v.w);
    }
}

// B tile from weight stored [n][k] (128 n x 32 k), transpose into Bs[k][n]
__device__ __forceinline__ void load_B_nk(const float* __restrict__ B, int ld, int tid,
                                          unsigned (*Bs)[132]) {
#pragma unroll
    for (int p = 0; p < 4; p++) {
        int idx = tid + p * 256;
        int n = idx >> 3, k4 = (idx & 7) << 2;
        float4 v = *(const float4*)(B + (size_t)n * ld + k4);
        Bs[k4 + 0][n] = f2tf32(v.x); Bs[k4 + 1][n] = f2tf32(v.y);
        Bs[k4 + 2][n] = f2tf32(v.z); Bs[k4 + 3][n] = f2tf32(v.w);
    }
}

// 8 warps: warp tile 64x32 inside 128x128 block tile; 4 k-substeps of 8
__device__ __forceinline__ void mma_tile_compute(const unsigned (*As)[36],
                                                 const unsigned (*Bs)[132],
                                                 int wm, int wn, int lane,
                                                 float acc[4][4][4]) {
    int g = lane >> 2, tg = lane & 3;
#pragma unroll
    for (int kk = 0; kk < 4; kk++) {
        int k = kk * 8;
        unsigned a[4][4], b[4][2];
#pragma unroll
        for (int im = 0; im < 4; im++) {
            int mb = wm * 64 + im * 16;
            a[im][0] = As[mb + g][k + tg];
            a[im][1] = As[mb + g + 8][k + tg];
            a[im][2] = As[mb + g][k + tg + 4];
            a[im][3] = As[mb + g + 8][k + tg + 4];
        }
#pragma unroll
        for (int jn = 0; jn < 4; jn++) {
            int nb = wn * 32 + jn * 8;
            b[jn][0] = Bs[k + tg][nb + g];
            b[jn][1] = Bs[k + tg + 4][nb + g];
        }
#pragma unroll
        for (int im = 0; im < 4; im++)
#pragma unroll
            for (int jn = 0; jn < 4; jn++)
                mma_tf32(acc[im][jn], a[im], b[jn]);
    }
}

// ---------------------------------------------------------------------------
// K1: t = X @ L^T   (M=8192, N=128, K=2048)
// ---------------------------------------------------------------------------
__global__ __launch_bounds__(256) void left_proj_mma(const float* __restrict__ X,
                                                     const float* __restrict__ L,
                                                     float* __restrict__ Tout) {
    __shared__ unsigned As[128][36];
    __shared__ unsigned Bs[32][132];
    int tid = threadIdx.x, lane = tid & 31, w = tid >> 5, wm = w >> 2, wn = w & 3;
    int m0 = blockIdx.x * 128;
    float acc[4][4][4] = {};
    for (int k0 = 0; k0 < Cdim; k0 += 32) {
        load_A(X + (size_t)m0 * Cdim + k0, Cdim, tid, As);
        load_B_nk(L + k0, Cdim, tid, Bs);
        __syncthreads();
        mma_tile_compute(As, Bs, wm, wn, lane, acc);
        __syncthreads();
    }
    int g = lane >> 2, tg = lane & 3;
#pragma unroll
    for (int im = 0; im < 4; im++)
#pragma unroll
        for (int jn = 0; jn < 4; jn++) {
            int r = m0 + wm * 64 + im * 16 + g;
            int c = wn * 32 + jn * 8 + tg * 2;
            Tout[(size_t)r * Rr + c]           = acc[im][jn][0];
            Tout[(size_t)r * Rr + c + 1]       = acc[im][jn][1];
            Tout[(size_t)(r + 8) * Rr + c]     = acc[im][jn][2];
            Tout[(size_t)(r + 8) * Rr + c + 1] = acc[im][jn][3];
        }
}

// ---------------------------------------------------------------------------
// K2: fused LORI output (blockdiag + low-rank + biases)
// grid = (BT/128, NB)
// ---------------------------------------------------------------------------
__global__ __launch_bounds__(256) void fused_out_mma(const float* __restrict__ X,
                                                     const float* __restrict__ Tl,
                                                     const float* __restrict__ Dg,
                                                     const float* __restrict__ RW,
                                                     const float* __restrict__ rb,
                                                     const float* __restrict__ bp,
                                                     float* __restrict__ Y) {
    __shared__ unsigned As[128][36];
    __shared__ unsigned Bs[32][132];
    int tid = threadIdx.x, lane = tid & 31, w = tid >> 5, wm = w >> 2, wn = w & 3;
    int m0 = blockIdx.x * 128;
    int nb = blockIdx.y;
    int c0 = nb * BS;
    const float* D = Dg + (size_t)nb * BS * BS;
    float acc[4][4][4] = {};

    // phase 1: block-diagonal, K = 128 (D stored [k][n])
    for (int k0 = 0; k0 < BS; k0 += 32) {
        load_A(X + (size_t)m0 * Cdim + c0 + k0, Cdim, tid, As);
        load_B_kn(D + (size_t)k0 * BS, BS, tid, Bs);
        __syncthreads();
        mma_tile_compute(As, Bs, wm, wn, lane, acc);
        __syncthreads();
    }
    // phase 2: low-rank, K = 128 (RW stored [n][k])
    for (int k0 = 0; k0 < Rr; k0 += 32) {
        load_A(Tl + (size_t)m0 * Rr + k0, Rr, tid, As);
        load_B_nk(RW + (size_t)c0 * Rr + k0, Rr, tid, Bs);
        __syncthreads();
        mma_tile_compute(As, Bs, wm, wn, lane, acc);
        __syncthreads();
    }

    int g = lane >> 2, tg = lane & 3;
#pragma unroll
    for (int im = 0; im < 4; im++)
#pragma unroll
        for (int jn = 0; jn < 4; jn++) {
            int r = m0 + wm * 64 + im * 16 + g;
            int cl = wn * 32 + jn * 8 + tg * 2;
            int c = c0 + cl;
            float b0 = rb[c] + bp[c], b1 = rb[c + 1] + bp[c + 1];
            Y[(size_t)r * Cdim + c]           = acc[im][jn][0] + b0;
            Y[(size_t)r * Cdim + c + 1]       = acc[im][jn][1] + b1;
            Y[(size_t)(r + 8) * Cdim + c]     = acc[im][jn][2] + b0;
            Y[(size_t)(r + 8) * Cdim + c + 1] = acc[im][jn][3] + b1;
        }
}

// ---------------------------------------------------------------------------
// K3: S tile = scale * Q @ K^T, 128x128 tiles, causal tiles only
// grid = (kt=16, qt=16, bh=64)
// ---------------------------------------------------------------------------
__global__ __launch_bounds__(256) void scores_mma(const float* __restrict__ Q,
                                                  const float* __restrict__ Kb) {
    int kt = blockIdx.x, qt = blockIdx.y, bh = blockIdx.z;
    if (kt > qt) return;
    int b = bh / H, h = bh % H;
    const float* Qp = Q + (size_t)b * Tdim * Cdim + (size_t)h * HD + (size_t)(qt * 128) * Cdim;
    const float* Kp = Kb + (size_t)b * Tdim * Cdim + (size_t)h * HD + (size_t)(kt * 128) * Cdim;
    __shared__ unsigned As[128][36];
    __shared__ unsigned Bs[32][132];
    int tid = threadIdx.x, lane = tid & 31, w = tid >> 5, wm = w >> 2, wn = w & 3;
    float acc[4][4][4] = {};
    for (int k0 = 0; k0 < HD; k0 += 32) {
        load_A(Qp + k0, Cdim, tid, As);
        load_B_nk(Kp + k0, Cdim, tid, Bs);
        __syncthreads();
        mma_tile_compute(As, Bs, wm, wn, lane, acc);
        __syncthreads();
    }
    float* Sp = g_S + (size_t)bh * Tdim * Tdim;
    int g = lane >> 2, tg = lane & 3;
#pragma unroll
    for (int im = 0; im < 4; im++)
#pragma unroll
        for (int jn = 0; jn < 4; jn++) {
            int r = qt * 128 + wm * 64 + im * 16 + g;
            int c = kt * 128 + wn * 32 + jn * 8 + tg * 2;
            Sp[(size_t)r * Tdim + c]           = acc[im][jn][0] * SCALE_ATT;
            Sp[(size_t)r * Tdim + c + 1]       = acc[im][jn][1] * SCALE_ATT;
            Sp[(size_t)(r + 8) * Tdim + c]     = acc[im][jn][2] * SCALE_ATT;
            Sp[(size_t)(r + 8) * Tdim + c + 1] = acc[im][jn][3] * SCALE_ATT;
        }
}

// ---------------------------------------------------------------------------
// K4: causal softmax, one warp per row; zero-fills diag-tile remainder (128)
// ---------------------------------------------------------------------------
__global__ void softmax_kernel() {
    int gw = (blockIdx.x * blockDim.x + threadIdx.x) >> 5;
    int lane = threadIdx.x & 31;
    int bh = gw / Tdim;
    int q = gw % Tdim;
    float* p = g_S + (size_t)bh * Tdim * Tdim + (size_t)q * Tdim;
    int len = q + 1;
    float m = -1e30f;
    for (int j = lane; j < len; j += 32) m = fmaxf(m, p[j]);
#pragma unroll
    for (int o = 16; o; o >>= 1) m = fmaxf(m, __shfl_xor_sync(0xffffffffu, m, o));
    float s = 0.f;
    for (int j = lane; j < len; j += 32) {
        float e = __expf(p[j] - m);
        p[j] = e;
        s += e;
    }
#pragma unroll
    for (int o = 16; o; o >>= 1) s += __shfl_xor_sync(0xffffffffu, s, o);
    float inv = 1.0f / s;
    for (int j = lane; j < len; j += 32) p[j] *= inv;
    int jend = ((q >> 7) + 1) << 7; // end of diagonal 128-tile
    for (int j = len + lane; j < jend; j += 32) p[j] = 0.f;
}

// ---------------------------------------------------------------------------
// K5: Y = P @ V over causal K-range. grid = (qt=16, bh=64)
// ---------------------------------------------------------------------------
__global__ __launch_bounds__(256) void pv_mma(const float* __restrict__ V,
                                              float* __restrict__ Y) {
    int qt = blockIdx.x, bh = blockIdx.y;
    int b = bh / H, h = bh % H;
    const float* Sp = g_S + (size_t)bh * Tdim * Tdim;
    const float* Vp = V + (size_t)b * Tdim * Cdim + (size_t)h * HD;
    float* Yp = Y + (size_t)b * Tdim * Cdim + (size_t)h * HD;
    __shared__ unsigned As[128][36];
    __shared__ unsigned Bs[32][132];
    int tid = threadIdx.x, lane = tid & 31, w = tid >> 5, wm = w >> 2, wn = w & 3;
    int m0 = qt * 128;
    float acc[4][4][4] = {};
    int klen = (qt + 1) * 128;
    for (int k0 = 0; k0 < klen; k0 += 32) {
        load_A(Sp + (size_t)m0 * Tdim + k0, Tdim, tid, As);
        load_B_kn(Vp + (size_t)k0 * Cdim, Cdim, tid, Bs);
        __syncthreads();
        mma_tile_compute(As, Bs, wm, wn, lane, acc);
        __syncthreads();
    }
    int g = lane >> 2, tg = lane & 3;
#pragma unroll
    for (int im = 0; im < 4; im++)
#pragma unroll
        for (int jn = 0; jn < 4; jn++) {
            int r = m0 + wm * 64 + im * 16 + g;
            int c = wn * 32 + jn * 8 + tg * 2;
            Yp[(size_t)r * Cdim + c]           = acc[im][jn][0];
            Yp[(size_t)r * Cdim + c + 1]       = acc[im][jn][1];
            Yp[(size_t)(r + 8) * Cdim + c]     = acc[im][jn][2];
            Yp[(size_t)(r + 8) * Cdim + c + 1] = acc[im][jn][3];
        }
}

// ---------------------------------------------------------------------------
extern "C" void kernel_launch(void* const* d_in, const int* in_sizes, int n_in,
                              void* d_out, int out_size) {
    const float* x    = (const float*)d_in[0];
    const float* diag = (const float*)d_in[1];
    const float* left = (const float*)d_in[2];
    const float* rw   = (const float*)d_in[3];
    const float* rb   = (const float*)d_in[4];
    const float* bp   = (const float*)d_in[5];
    float* out = (float*)d_out;

    float *pt, *pq, *pk, *pv, *py;
    cudaGetSymbolAddress((void**)&pt, g_t);
    cudaGetSymbolAddress((void**)&pq, g_q);
    cudaGetSymbolAddress((void**)&pk, g_k);
    cudaGetSymbolAddress((void**)&pv, g_v);
    cudaGetSymbolAddress((void**)&py, g_y);

    float* dst[3] = {pq, pk, pv};
    for (int i = 0; i < 3; i++) {
        left_proj_mma<<<BT / 128, 256>>>(x, left + (size_t)i * Rr * Cdim, pt);
        fused_out_mma<<<dim3(BT / 128, NB), 256>>>(
            x, pt,
            diag + (size_t)i * NB * BS * BS,
            rw + (size_t)i * Cdim * Rr,
            rb + (size_t)i * Cdim,
            bp + (size_t)i * Cdim,
            dst[i]);
    }

    scores_mma<<<dim3(16, 16, NBH), 256>>>(pq, pk);
    softmax_kernel<<<(NBH * Tdim) / 8, 256>>>();
    pv_mma<<<dim3(16, NBH), 256>>>(pv, py);

    left_proj_mma<<<BT / 128, 256>>>(py, left + (size_t)3 * Rr * Cdim, pt);
    fused_out_mma<<<dim3(BT / 128, NB), 256>>>(
        py, pt,
        diag + (size_t)3 * NB * BS * BS,
        rw + (size_t)3 * Cdim * Rr,
        rb + (size_t)3 * Cdim,
        bp + (size_t)3 * Cdim,
        out);
}